// round 4
// baseline (speedup 1.0000x reference)
#include <cuda_runtime.h>
#include <cuda_bf16.h>

// GruDirection3d forward wavefront:
//   out[d,y,x] = z*h_tilde + (1-z)*out[d-1,y-1,x-1],  border -> h0
//
// Shifted coordinates u=y-d, v=x-d: 63x63 independent serial scans along d
// (addr = base0 + d*1057). No smem, no barriers, coalesced among active lanes,
// every voxel touched exactly once (minimal 75.5MB traffic).
//
// R3 lesson: guarded loads -> ptxas serialized (regs=16, zero MLP). Fix:
// loads are UNCONDITIONAL with window-clamped address (idx 0 always valid),
// depth-8 register pipeline with compile-time stage index -> 16 LDGs in
// flight per thread.

#define VOLE 32768              // 32*32*32 elements per (b,c) volume
#define STEP 1057               // 1024 + 32 + 1: address delta per d along a chain
#define PD   8                  // pipeline depth

__global__ __launch_bounds__(256)
void gru3d_chain(const float* __restrict__ z,
                 const float* __restrict__ ht,
                 const float* __restrict__ h0p,
                 float*       __restrict__ out)
{
    const float h0 = __ldg(h0p);
    const int tid  = threadIdx.x;

    // 64 lanes of v per u-row; 4 u-rows per CTA; 16 CTAs cover all u.
    const int v   = (tid & 63) - 32;                                 // -32..31
    const int u   = ((int)(blockIdx.x & 15)) * 4 + (tid >> 6) - 31;  // -31..32
    const int vol = blockIdx.x >> 4;

    // Active window in d: both u+d and v+d in [0,32).
    int d0 = 0;
    if (-u > d0) d0 = -u;
    if (-v > d0) d0 = -v;
    int d1 = 32;
    if (32 - u < d1) d1 = 32 - u;
    if (32 - v < d1) d1 = 32 - v;

    const size_t vbase = (size_t)vol * VOLE;
    const float* zp = z  + vbase;
    const float* hp = ht + vbase;
    float*       op = out + vbase;

    const int base0 = u * 32 + v;

    // Prologue: stages 0..PD-1 in flight (clamped, unconditional).
    float zb[PD], hb[PD];
    #pragma unroll
    for (int s = 0; s < PD; ++s) {
        const bool act = (s >= d0) && (s < d1);
        const int idx = act ? (base0 + s * STEP) : 0;
        zb[s] = zp[idx];
        hb[s] = hp[idx];
    }

    float o = h0;   // window start always borders h0 (one of d,u+d,v+d is 0)

    #pragma unroll
    for (int d = 0; d < 32; ++d) {
        const int s = d & (PD - 1);
        const float zz = zb[s];
        const float hh = hb[s];

        // Refill this stage with step d+PD (unconditional, clamped address).
        if (d + PD < 32) {
            const int dn = d + PD;
            const bool act = (dn >= d0) && (dn < d1);
            const int idx = act ? (base0 + dn * STEP) : 0;
            zb[s] = zp[idx];
            hb[s] = hp[idx];
        }

        if (d >= d0 && d < d1) {
            o = fmaf(zz, hh - o, o);          // z*ht + (1-z)*prev
            op[base0 + d * STEP] = o;
        }
    }
}

extern "C" void kernel_launch(void* const* d_in, const int* in_sizes, int n_in,
                              void* d_out, int out_size)
{
    const float* z  = (const float*)d_in[0];
    const float* ht = (const float*)d_in[1];
    const float* h0 = (const float*)d_in[2];
    float* out = (float*)d_out;

    const int n_volumes = out_size / VOLE;   // B*C = 192
    gru3d_chain<<<n_volumes * 16, 256>>>(z, ht, h0, out);
}

// round 5
// speedup vs baseline: 1.1951x; 1.1951x over previous
#include <cuda_runtime.h>
#include <cuda_bf16.h>

// GruDirection3d forward wavefront:
//   out[d,y,x] = z*h_tilde + (1-z)*out[d-1,y-1,x-1],  border -> h0
//
// Shift ONLY y: u = y - d. Then out[d, u+d, x] depends on
// out[d-1, u+(d-1), x-1]  ==  same u-chain, previous step, lane x-1.
// One WARP per (volume, u) chain: lanes = x, the y-shift vanishes, the
// x-shift is __shfl_up within the warp (lane 0 -> h0 border). No smem, no
// barriers, no cross-warp traffic. Each step the warp reads/writes one
// aligned 128B row (idx = u*32 + d*1056, both 32-float multiples), every
// voxel touched exactly once (minimal DRAM traffic). Loads are address-
// independent of the accumulator -> depth-4 clamped register prefetch.

#define VOLE  32768    // 32^3
#define STEPW 1056     // 1024 + 32: index delta per d along a (vol,u) chain
#define NU    63       // u in [-31, 31]

__global__ __launch_bounds__(256)
void gru3d_warp(const float* __restrict__ z,
                const float* __restrict__ ht,
                const float* __restrict__ h0p,
                float*       __restrict__ out)
{
    const float h0  = __ldg(h0p);
    const int lane  = threadIdx.x & 31;
    const int w     = blockIdx.x * 8 + (threadIdx.x >> 5);   // global warp id
    const int vol   = w / NU;
    const int u     = (w % NU) - 31;                          // -31..31

    const int n = 32 - (u < 0 ? -u : u);        // active steps along d
    // index at first active step (d0 = max(0,-u)): d0*1056 + u*32
    const int idx0 = (u >= 0 ? u * 32 : -1024 * u) + lane;

    const size_t vb = (size_t)vol * VOLE;
    const float* zp = z  + vb + idx0;
    const float* hp = ht + vb + idx0;
    float*       op = out + vb + idx0;

    // Depth-4 prefetch pipeline (clamped addresses; always in-bounds).
    float zb[4], hb[4];
    #pragma unroll
    for (int s = 0; s < 4; ++s) {
        const int t = (s < n) ? s : (n - 1);
        zb[s] = zp[t * STEPW];
        hb[s] = hp[t * STEPW];
    }

    // At the first active step prev plane/row is the h0 border for all lanes.
    float o = h0;

    #pragma unroll 4
    for (int i = 0; i < n; ++i) {
        const int s = i & 3;
        const float zz = zb[s];
        const float hh = hb[s];

        // Refill stage with step i+4 (clamped -> unconditional, L1-hit dups).
        const int t = (i + 4 < n) ? (i + 4) : (n - 1);
        zb[s] = zp[t * STEPW];
        hb[s] = hp[t * STEPW];

        float pl = __shfl_up_sync(0xffffffffu, o, 1);
        if (lane == 0) pl = h0;                  // x-1 < 0 -> border
        o = fmaf(zz, hh - pl, pl);               // z*ht + (1-z)*prev
        op[i * STEPW] = o;
    }
}

extern "C" void kernel_launch(void* const* d_in, const int* in_sizes, int n_in,
                              void* d_out, int out_size)
{
    const float* z  = (const float*)d_in[0];
    const float* ht = (const float*)d_in[1];
    const float* h0 = (const float*)d_in[2];
    float* out = (float*)d_out;

    const int n_volumes = out_size / VOLE;          // B*C = 192
    const int n_warps   = n_volumes * NU;           // 12096
    gru3d_warp<<<n_warps / 8, 256>>>(z, ht, h0, out);
}

// round 6
// speedup vs baseline: 1.9649x; 1.6441x over previous
#include <cuda_runtime.h>
#include <cuda_bf16.h>

// GruDirection3d forward wavefront:
//   out[d,y,x] = z*h_tilde + (1-z)*out[d-1,y-1,x-1],  border -> h0
//
// R1 architecture (best so far): one CTA of 1024 threads per (b,c) volume,
// plane sweep over d, previous output plane in a double-buffered 33x33 smem
// tile whose row-0/col-0 border stays h0. R6 delta: depth-4 rotating register
// pipeline on the z/h_tilde plane loads (planes d..d+3 in flight, 8 LDG lines
// per warp instead of 2) to lift the per-SM MLP ceiling that bounded R1's
// imbalanced tail. Thread count stays 1024 (R2 showed occupancy, not pipeline
// depth, was the lever we must not trade away).

#define DDIM 32
#define PLANE 1024     // 32*32
#define EXT 33
#define PD 4           // pipeline depth

__global__ __launch_bounds__(1024, 1)
void gru3d_kernel(const float* __restrict__ z,
                  const float* __restrict__ ht,
                  const float* __restrict__ h0p,
                  float* __restrict__ out)
{
    __shared__ float buf[2][EXT * EXT];

    const float h0 = __ldg(h0p);
    const int tid = threadIdx.x;

    // Init both buffers (interior overwritten; border row/col stay h0).
    #pragma unroll
    for (int i = tid; i < 2 * EXT * EXT; i += 1024)
        (&buf[0][0])[i] = h0;

    const int y = tid >> 5;
    const int x = tid & 31;

    const size_t base = (size_t)blockIdx.x * (DDIM * PLANE) + (size_t)(y * 32 + x);
    const float* zp = z  + base;
    const float* hp = ht + base;
    float*       op = out + base;

    // Prologue: planes 0..PD-1 in flight.
    float zb[PD], hb[PD];
    #pragma unroll
    for (int s = 0; s < PD; ++s) {
        zb[s] = zp[(size_t)s * PLANE];
        hb[s] = hp[(size_t)s * PLANE];
    }

    __syncthreads();   // buf init complete

    const int ridx = y * EXT + x;              // read: prev[y-1][x-1] (ext coords)
    const int widx = (y + 1) * EXT + (x + 1);  // write: out[y][x]

    #pragma unroll
    for (int d = 0; d < DDIM; ++d) {
        const int s = d & (PD - 1);
        const float zc = zb[s];
        const float hc = hb[s];

        // Refill this stage with plane d+PD (PD iterations of latency cover).
        if (d + PD < DDIM) {
            zb[s] = zp[(size_t)(d + PD) * PLANE];
            hb[s] = hp[(size_t)(d + PD) * PLANE];
        }

        const float p = buf[(d + 1) & 1][ridx];

        // z*ht + (1-z)*p  ==  p + z*(ht - p)
        const float o = fmaf(zc, hc - p, p);

        buf[d & 1][widx] = o;
        op[(size_t)d * PLANE] = o;

        __syncthreads();   // writes of step d visible before reads of step d+1
    }
}

extern "C" void kernel_launch(void* const* d_in, const int* in_sizes, int n_in,
                              void* d_out, int out_size)
{
    const float* z  = (const float*)d_in[0];
    const float* ht = (const float*)d_in[1];
    const float* h0 = (const float*)d_in[2];
    float* out = (float*)d_out;

    const int n_volumes = out_size / (DDIM * PLANE);   // B*C = 192
    gru3d_kernel<<<n_volumes, 1024>>>(z, ht, h0, out);
}